// round 11
// baseline (speedup 1.0000x reference)
#include <cuda_runtime.h>
#include <cstdint>
#include <mma.h>

using namespace nvcuda;

#define HIDDEN 768
#define BATCH  4
#define SEQ    4096

// ---- scratch (device globals: allocation-free rule) ----
__device__ float g_Q [BATCH * SEQ * HIDDEN];                 // 48 MB
__device__ float g_K [BATCH * SEQ * HIDDEN];                 // 48 MB
__device__ float g_Vt[BATCH * HIDDEN * SEQ];                 // 48 MB (V^T per batch)
__device__ float g_S [(long long)BATCH * SEQ * SEQ];         // 256 MB
__device__ float g_X [BATCH * SEQ * HIDDEN];                 // 48 MB (tf32-rounded x)
__device__ float g_W [3 * HIDDEN * HIDDEN];                  // 7 MB  (tf32-rounded Wq|Wk|Wv)

// ===========================================================================
// TF32 wmma GEMM (HMMA fallback path; compute_103 lowers no tcgen05):
//   C[M,N] = A[M,K] @ B^T (+bias),  B stored [N,K] row-major (K-major)
// Block 128x128, 4 warps (128 thr), warp tile 64x64 -> 16 wmma accs.
// ALL operands are pre-rounded to tf32-representable fp32 in memory, so the
// mainloop feeds raw bits (truncation == identity) -> zero cvt instructions.
// ROUND_OUT rounds C to tf32 in the epilogue (for operands of later GEMMs).
// STORE_T stores C transposed (to produce V^T).
// ===========================================================================
constexpr int BM = 128, BN = 128, BK = 32;
constexpr int BKP = 36;                        // padded ld, k-contiguous tiles

constexpr int A_TILE_F = BM * BKP;             // 4608 floats
constexpr int STAGE_F  = 2 * A_TILE_F;         // A+B = 9216 floats
constexpr int NSTAGE   = 3;
constexpr int SMEM_F   = NSTAGE * STAGE_F;     // 27648 floats = 110592 B
constexpr int EPI_LD   = 68;                   // epilogue scratch ld

__device__ __forceinline__ void cp_async16(void* sdst, const void* gsrc) {
    unsigned int s = (unsigned int)__cvta_generic_to_shared(sdst);
    asm volatile("cp.async.cg.shared.global [%0], [%1], 16;\n" :: "r"(s), "l"(gsrc));
}
__device__ __forceinline__ void cp_commit() {
    asm volatile("cp.async.commit_group;\n");
}
template <int N_> __device__ __forceinline__ void cp_wait() {
    asm volatile("cp.async.wait_group %0;\n" :: "n"(N_));
}
__device__ __forceinline__ float rn_tf32(float v) {
    float r;
    asm("cvt.rna.tf32.f32 %0, %1;" : "=f"(r) : "f"(v));
    return r;
}

template <bool STORE_T, bool ROUND_OUT>
__global__ __launch_bounds__(128, 2)
void tf32_gemm(const float* __restrict__ A, const float* __restrict__ B,
               float* __restrict__ Cn, float* __restrict__ Ct,
               const float* __restrict__ bias,
               int N, int ldct, int K,
               long long sA, long long sB, long long sC)
{
    extern __shared__ float smem[];

    const int tid  = threadIdx.x;
    const int warp = tid >> 5;
    const int lane = tid & 31;
    const int m0 = blockIdx.y * BM;
    const int n0 = blockIdx.x * BN;
    const int z  = blockIdx.z;

    const float* Ab = A + z * sA + (long long)m0 * K;
    const float* Bb = B + z * sB + (long long)n0 * K;

    const int wm = (warp >> 1) * 64;     // 0 / 64
    const int wn = (warp & 1) * 64;      // 0 / 64

    wmma::fragment<wmma::accumulator, 16, 16, 8, float> acc[4][4];
#pragma unroll
    for (int i = 0; i < 4; i++)
#pragma unroll
        for (int j = 0; j < 4; j++)
            wmma::fill_fragment(acc[i][j], 0.0f);

    // ---- async tile loader: A[128x32] + B[128x32], k-contiguous float4 ----
    auto load = [&](int stage, int t) {
        float* As = smem + stage * STAGE_F;
        float* Bs = As + A_TILE_F;
        const int kb = t * BK;
#pragma unroll
        for (int i = 0; i < 8; i++) {
            int idx = tid + (i << 7);          // 0..1023
            int r = idx >> 3;                  // row 0..127
            int c = (idx & 7) << 2;            // col 0,4,..,28
            cp_async16(&As[r * BKP + c], Ab + (long long)r * K + kb + c);
            cp_async16(&Bs[r * BKP + c], Bb + (long long)r * K + kb + c);
        }
        cp_commit();
    };

    const int T = K / BK;
    load(0, 0);
    load(1, 1);
    load(2, 2);

    for (int t = 0; t < T; t++) {
        const int rem = T - 1 - t;
        if (rem >= 2)      cp_wait<2>();
        else if (rem == 1) cp_wait<1>();
        else               cp_wait<0>();
        __syncthreads();

        const int st = t % 3;
        const float* As = smem + st * STAGE_F;
        const float* Bs = As + A_TILE_F;

#pragma unroll
        for (int kk = 0; kk < BK; kk += 8) {
            wmma::fragment<wmma::matrix_a, 16, 16, 8,
                           wmma::precision::tf32, wmma::row_major> af[4];
            wmma::fragment<wmma::matrix_b, 16, 16, 8,
                           wmma::precision::tf32, wmma::col_major> bf[4];
#pragma unroll
            for (int i = 0; i < 4; i++)
                wmma::load_matrix_sync(af[i], &As[(wm + i * 16) * BKP + kk], BKP);
#pragma unroll
            for (int j = 0; j < 4; j++)
                wmma::load_matrix_sync(bf[j], &Bs[(wn + j * 16) * BKP + kk], BKP);
            // no cvt: operands are pre-rounded tf32-representable fp32
#pragma unroll
            for (int i = 0; i < 4; i++)
#pragma unroll
                for (int j = 0; j < 4; j++)
                    wmma::mma_sync(acc[i][j], af[i], bf[j], acc[i][j]);
        }
        __syncthreads();
        if (t + 3 < T) load(st, t + 3);
    }

    // ---- epilogue: stage 64x64 per warp in smem, coalesced global writes ----
    float* scr = smem + warp * (64 * EPI_LD);
#pragma unroll
    for (int i = 0; i < 4; i++)
#pragma unroll
        for (int j = 0; j < 4; j++)
            wmma::store_matrix_sync(&scr[(i * 16) * EPI_LD + j * 16], acc[i][j],
                                    EPI_LD, wmma::mem_row_major);
    __syncwarp();

    if constexpr (STORE_T) {
        // write C^T: lanes sweep m (coalesced), loop over n
        float* ct = Ct + z * sC;
        const int mA = m0 + wm + lane;
        const int mB = mA + 32;
#pragma unroll 4
        for (int j = 0; j < 64; j++) {
            float bb = bias ? bias[n0 + wn + j] : 0.0f;
            long long rowo = (long long)(n0 + wn + j) * ldct;
            float v0 = scr[lane * EPI_LD + j] + bb;
            float v1 = scr[(lane + 32) * EPI_LD + j] + bb;
            if (ROUND_OUT) { v0 = rn_tf32(v0); v1 = rn_tf32(v1); }
            ct[rowo + mA] = v0;
            ct[rowo + mB] = v1;
        }
    } else {
        float* cn = Cn + z * sC;
        const float b0 = bias ? bias[n0 + wn + lane] : 0.0f;
        const float b1 = bias ? bias[n0 + wn + 32 + lane] : 0.0f;
#pragma unroll 4
        for (int r = 0; r < 64; r++) {
            long long rowo = (long long)(m0 + wm + r) * N + n0 + wn;
            float v0 = scr[r * EPI_LD + lane]      + b0;
            float v1 = scr[r * EPI_LD + 32 + lane] + b1;
            if (ROUND_OUT) { v0 = rn_tf32(v0); v1 = rn_tf32(v1); }
            cn[rowo + lane]      = v0;
            cn[rowo + 32 + lane] = v1;
        }
    }
}

// ---------------------------------------------------------------------------
// Elementwise RN-round to tf32-representable fp32 (vectorized float4).
// ---------------------------------------------------------------------------
__global__ void round_tf32_kernel(const float4* __restrict__ in,
                                  float4* __restrict__ out, int n4)
{
    int i = blockIdx.x * blockDim.x + threadIdx.x;
    if (i >= n4) return;
    float4 v = in[i];
    v.x = rn_tf32(v.x); v.y = rn_tf32(v.y);
    v.z = rn_tf32(v.z); v.w = rn_tf32(v.w);
    out[i] = v;
}

// ---------------------------------------------------------------------------
// Row softmax over SEQ=4096, scale folded in; output RN-rounded to tf32.
// One block (256 thr) per row.
// ---------------------------------------------------------------------------
__global__ __launch_bounds__(256)
void softmax_kernel(float* __restrict__ S, float scale)
{
    long long row = blockIdx.x;
    float* p = S + row * (long long)SEQ;
    const int tid  = threadIdx.x;
    const int warp = tid >> 5;
    const int lane = tid & 31;

    __shared__ float red[8];
    __shared__ float bval;

    float v[16];
    float mx = -1e30f;
#pragma unroll
    for (int i = 0; i < 16; i++) {
        v[i] = p[i * 256 + tid] * scale;
        mx = fmaxf(mx, v[i]);
    }
#pragma unroll
    for (int o = 16; o > 0; o >>= 1)
        mx = fmaxf(mx, __shfl_xor_sync(0xffffffffu, mx, o));
    if (lane == 0) red[warp] = mx;
    __syncthreads();
    if (tid == 0) {
        float m = red[0];
#pragma unroll
        for (int i = 1; i < 8; i++) m = fmaxf(m, red[i]);
        bval = m;
    }
    __syncthreads();
    mx = bval;
    __syncthreads();

    float sum = 0.0f;
#pragma unroll
    for (int i = 0; i < 16; i++) {
        v[i] = __expf(v[i] - mx);
        sum += v[i];
    }
#pragma unroll
    for (int o = 16; o > 0; o >>= 1)
        sum += __shfl_xor_sync(0xffffffffu, sum, o);
    if (lane == 0) red[warp] = sum;
    __syncthreads();
    if (tid == 0) {
        float s = 0.0f;
#pragma unroll
        for (int i = 0; i < 8; i++) s += red[i];
        bval = s;
    }
    __syncthreads();
    float inv = 1.0f / bval;
#pragma unroll
    for (int i = 0; i < 16; i++)
        p[i * 256 + tid] = rn_tf32(v[i] * inv);
}

// ---------------------------------------------------------------------------
// Launch
// ---------------------------------------------------------------------------
extern "C" void kernel_launch(void* const* d_in, const int* in_sizes, int n_in,
                              void* d_out, int out_size)
{
    const float* x  = (const float*)d_in[0];
    const float* Wq = (const float*)d_in[1];
    const float* bq = (const float*)d_in[2];
    const float* Wk = (const float*)d_in[3];
    const float* bk = (const float*)d_in[4];
    const float* Wv = (const float*)d_in[5];
    const float* bv = (const float*)d_in[6];
    float* out = (float*)d_out;

    float *Qp, *Kp, *Vtp, *Sp, *Xp, *Wp;
    cudaGetSymbolAddress((void**)&Qp,  g_Q);
    cudaGetSymbolAddress((void**)&Kp,  g_K);
    cudaGetSymbolAddress((void**)&Vtp, g_Vt);
    cudaGetSymbolAddress((void**)&Sp,  g_S);
    cudaGetSymbolAddress((void**)&Xp,  g_X);
    cudaGetSymbolAddress((void**)&Wp,  g_W);

    const int smemBytes = SMEM_F * (int)sizeof(float);     // 110592
    cudaFuncSetAttribute((const void*)tf32_gemm<false, true>,
                         cudaFuncAttributeMaxDynamicSharedMemorySize, smemBytes);
    cudaFuncSetAttribute((const void*)tf32_gemm<false, false>,
                         cudaFuncAttributeMaxDynamicSharedMemorySize, smemBytes);
    cudaFuncSetAttribute((const void*)tf32_gemm<true, true>,
                         cudaFuncAttributeMaxDynamicSharedMemorySize, smemBytes);

    const long long SH = (long long)SEQ * HIDDEN;
    const long long SS = (long long)SEQ * SEQ;
    const int WN = HIDDEN * HIDDEN;                         // 589824

    // 0) pre-round inputs to tf32-representable fp32
    {
        int n4x = BATCH * SEQ * HIDDEN / 4;                 // 3,145,728
        round_tf32_kernel<<<(n4x + 255) / 256, 256>>>((const float4*)x, (float4*)Xp, n4x);
        int n4w = WN / 4;
        round_tf32_kernel<<<(n4w + 255) / 256, 256>>>((const float4*)Wq, (float4*)(Wp), n4w);
        round_tf32_kernel<<<(n4w + 255) / 256, 256>>>((const float4*)Wk, (float4*)(Wp + WN), n4w);
        round_tf32_kernel<<<(n4w + 255) / 256, 256>>>((const float4*)Wv, (float4*)(Wp + 2 * WN), n4w);
    }

    // 1) QKV projections (per batch): [4096,768] = x_b @ W^T + b, outputs rounded.
    //    V stored transposed (Vt[b][h][s]) so the PV GEMM reads K-major B.
    {
        dim3 g(HIDDEN / BN, SEQ / BM, BATCH);   // (6, 32, 4)
        tf32_gemm<false, true><<<g, 128, smemBytes>>>(Xp, Wp, Qp, nullptr, bq,
                                                      HIDDEN, 0, HIDDEN, SH, 0, SH);
        tf32_gemm<false, true><<<g, 128, smemBytes>>>(Xp, Wp + WN, Kp, nullptr, bk,
                                                      HIDDEN, 0, HIDDEN, SH, 0, SH);
        tf32_gemm<true,  true><<<g, 128, smemBytes>>>(Xp, Wp + 2 * WN, nullptr, Vtp, bv,
                                                      HIDDEN, SEQ, HIDDEN, SH, 0, SH);
    }

    // 2) scores: S_b = Q_b @ K_b^T  (full fp32 out; rounded by softmax)
    {
        dim3 g(SEQ / BN, SEQ / BM, BATCH);      // (32, 32, 4)
        tf32_gemm<false, false><<<g, 128, smemBytes>>>(Qp, Kp, Sp, nullptr, nullptr,
                                                       SEQ, 0, HIDDEN, SH, SH, SS);
    }

    // 3) softmax rows (scale folded in, P rounded to tf32)
    {
        float scale = 1.0f / sqrtf((float)HIDDEN);
        softmax_kernel<<<BATCH * SEQ, 256>>>(Sp, scale);
    }

    // 4) output: O_b = P_b @ V_b   (Vt is [HIDDEN, SEQ] K-major, K = SEQ)
    {
        dim3 g(HIDDEN / BN, SEQ / BM, BATCH);   // (6, 32, 4)
        tf32_gemm<false, false><<<g, 128, smemBytes>>>(Sp, Vtp, out, nullptr, nullptr,
                                                       HIDDEN, 0, SEQ, SS, SH, SH);
    }
}

// round 12
// speedup vs baseline: 1.4455x; 1.4455x over previous
#include <cuda_runtime.h>
#include <cstdint>
#include <mma.h>

using namespace nvcuda;

#define HIDDEN 768
#define BATCH  4
#define SEQ    4096

// ---- scratch (device globals: allocation-free rule) ----
__device__ float g_Q [BATCH * SEQ * HIDDEN];                 // 48 MB
__device__ float g_K [BATCH * SEQ * HIDDEN];                 // 48 MB
__device__ float g_Vt[BATCH * HIDDEN * SEQ];                 // 48 MB (V^T per batch)
__device__ float g_S [(long long)BATCH * SEQ * SEQ];         // 256 MB
__device__ float g_X [BATCH * SEQ * HIDDEN];                 // 48 MB (tf32-rounded x)
__device__ float g_W [3 * HIDDEN * HIDDEN];                  // 7 MB  (tf32-rounded Wq|Wk|Wv)

// ===========================================================================
// TF32 wmma GEMM (HMMA path):  C[M,N] = A[M,K] @ B^T (+bias), B stored [N,K].
// Block 128x128, 8 warps (256 thr, 2x4), warp tile 64x32 -> 8 wmma accs.
// Operands pre-rounded to tf32-representable fp32 -> zero cvt in mainloop.
// 3-stage cp.async pipeline. ROUND_OUT rounds C in epilogue; STORE_T writes C^T.
// ===========================================================================
constexpr int BM = 128, BN = 128, BK = 32;
constexpr int BKP = 36;                        // padded ld, k-contiguous tiles

constexpr int A_TILE_F = BM * BKP;             // 4608 floats
constexpr int STAGE_F  = 2 * A_TILE_F;         // A+B = 9216 floats
constexpr int NSTAGE   = 3;
constexpr int SMEM_F   = NSTAGE * STAGE_F;     // 27648 floats = 110592 B
constexpr int EPI_LD   = 36;                   // epilogue scratch ld (64x32 tile)

__device__ __forceinline__ void cp_async16(void* sdst, const void* gsrc) {
    unsigned int s = (unsigned int)__cvta_generic_to_shared(sdst);
    asm volatile("cp.async.cg.shared.global [%0], [%1], 16;\n" :: "r"(s), "l"(gsrc));
}
__device__ __forceinline__ void cp_commit() {
    asm volatile("cp.async.commit_group;\n");
}
template <int N_> __device__ __forceinline__ void cp_wait() {
    asm volatile("cp.async.wait_group %0;\n" :: "n"(N_));
}
__device__ __forceinline__ float rn_tf32(float v) {
    float r;
    asm("cvt.rna.tf32.f32 %0, %1;" : "=f"(r) : "f"(v));
    return r;
}

template <bool STORE_T, bool ROUND_OUT>
__global__ __launch_bounds__(256, 2)
void tf32_gemm(const float* __restrict__ A, const float* __restrict__ B,
               float* __restrict__ Cn, float* __restrict__ Ct,
               const float* __restrict__ bias,
               int N, int ldct, int K,
               long long sA, long long sB, long long sC)
{
    extern __shared__ float smem[];

    const int tid  = threadIdx.x;
    const int warp = tid >> 5;
    const int lane = tid & 31;
    const int m0 = blockIdx.y * BM;
    const int n0 = blockIdx.x * BN;
    const int z  = blockIdx.z;

    const float* Ab = A + z * sA + (long long)m0 * K;
    const float* Bb = B + z * sB + (long long)n0 * K;

    const int wm = (warp >> 2) * 64;     // 0 / 64
    const int wn = (warp & 3) * 32;      // 0/32/64/96

    wmma::fragment<wmma::accumulator, 16, 16, 8, float> acc[4][2];
#pragma unroll
    for (int i = 0; i < 4; i++)
#pragma unroll
        for (int j = 0; j < 2; j++)
            wmma::fill_fragment(acc[i][j], 0.0f);

    // ---- async tile loader: A[128x32] + B[128x32], k-contiguous float4 ----
    auto load = [&](int stage, int t) {
        float* As = smem + stage * STAGE_F;
        float* Bs = As + A_TILE_F;
        const int kb = t * BK;
#pragma unroll
        for (int i = 0; i < 4; i++) {
            int idx = tid + (i << 8);          // 0..1023
            int r = idx >> 3;                  // row 0..127
            int c = (idx & 7) << 2;            // col 0,4,..,28
            cp_async16(&As[r * BKP + c], Ab + (long long)r * K + kb + c);
            cp_async16(&Bs[r * BKP + c], Bb + (long long)r * K + kb + c);
        }
        cp_commit();
    };

    const int T = K / BK;
    load(0, 0);
    load(1, 1);
    load(2, 2);

    for (int t = 0; t < T; t++) {
        const int rem = T - 1 - t;
        if (rem >= 2)      cp_wait<2>();
        else if (rem == 1) cp_wait<1>();
        else               cp_wait<0>();
        __syncthreads();

        const int st = t % 3;
        const float* As = smem + st * STAGE_F;
        const float* Bs = As + A_TILE_F;

#pragma unroll
        for (int kk = 0; kk < BK; kk += 8) {
            wmma::fragment<wmma::matrix_a, 16, 16, 8,
                           wmma::precision::tf32, wmma::row_major> af[4];
            wmma::fragment<wmma::matrix_b, 16, 16, 8,
                           wmma::precision::tf32, wmma::col_major> bf[2];
#pragma unroll
            for (int i = 0; i < 4; i++)
                wmma::load_matrix_sync(af[i], &As[(wm + i * 16) * BKP + kk], BKP);
#pragma unroll
            for (int j = 0; j < 2; j++)
                wmma::load_matrix_sync(bf[j], &Bs[(wn + j * 16) * BKP + kk], BKP);
            // no cvt: operands are pre-rounded tf32-representable fp32
#pragma unroll
            for (int i = 0; i < 4; i++)
#pragma unroll
                for (int j = 0; j < 2; j++)
                    wmma::mma_sync(acc[i][j], af[i], bf[j], acc[i][j]);
        }
        __syncthreads();
        if (t + 3 < T) load(st, t + 3);
    }

    // ---- epilogue: stage 64x32 per warp in smem, coalesced global writes ----
    float* scr = smem + warp * (64 * EPI_LD);
#pragma unroll
    for (int i = 0; i < 4; i++)
#pragma unroll
        for (int j = 0; j < 2; j++)
            wmma::store_matrix_sync(&scr[(i * 16) * EPI_LD + j * 16], acc[i][j],
                                    EPI_LD, wmma::mem_row_major);
    __syncwarp();

    if constexpr (STORE_T) {
        // write C^T: lanes sweep m (coalesced), loop over the 32 n-cols
        float* ct = Ct + z * sC;
        const int mA = m0 + wm + lane;
        const int mB = mA + 32;
#pragma unroll 4
        for (int j = 0; j < 32; j++) {
            float bb = bias ? bias[n0 + wn + j] : 0.0f;
            long long rowo = (long long)(n0 + wn + j) * ldct;
            float v0 = scr[lane * EPI_LD + j] + bb;
            float v1 = scr[(lane + 32) * EPI_LD + j] + bb;
            if (ROUND_OUT) { v0 = rn_tf32(v0); v1 = rn_tf32(v1); }
            ct[rowo + mA] = v0;
            ct[rowo + mB] = v1;
        }
    } else {
        float* cn = Cn + z * sC;
        const float bb = bias ? bias[n0 + wn + lane] : 0.0f;
#pragma unroll 8
        for (int r = 0; r < 64; r++) {
            float v = scr[r * EPI_LD + lane] + bb;
            if (ROUND_OUT) v = rn_tf32(v);
            cn[(long long)(m0 + wm + r) * N + n0 + wn + lane] = v;
        }
    }
}

// ---------------------------------------------------------------------------
// Elementwise RN-round to tf32-representable fp32 (vectorized float4).
// ---------------------------------------------------------------------------
__global__ void round_tf32_kernel(const float4* __restrict__ in,
                                  float4* __restrict__ out, int n4)
{
    int i = blockIdx.x * blockDim.x + threadIdx.x;
    if (i >= n4) return;
    float4 v = in[i];
    v.x = rn_tf32(v.x); v.y = rn_tf32(v.y);
    v.z = rn_tf32(v.z); v.w = rn_tf32(v.w);
    out[i] = v;
}

// ---------------------------------------------------------------------------
// Row softmax over SEQ=4096, scale folded in; output RN-rounded to tf32.
// One block (256 thr) per row.
// ---------------------------------------------------------------------------
__global__ __launch_bounds__(256)
void softmax_kernel(float* __restrict__ S, float scale)
{
    long long row = blockIdx.x;
    float* p = S + row * (long long)SEQ;
    const int tid  = threadIdx.x;
    const int warp = tid >> 5;
    const int lane = tid & 31;

    __shared__ float red[8];
    __shared__ float bval;

    float v[16];
    float mx = -1e30f;
#pragma unroll
    for (int i = 0; i < 16; i++) {
        v[i] = p[i * 256 + tid] * scale;
        mx = fmaxf(mx, v[i]);
    }
#pragma unroll
    for (int o = 16; o > 0; o >>= 1)
        mx = fmaxf(mx, __shfl_xor_sync(0xffffffffu, mx, o));
    if (lane == 0) red[warp] = mx;
    __syncthreads();
    if (tid == 0) {
        float m = red[0];
#pragma unroll
        for (int i = 1; i < 8; i++) m = fmaxf(m, red[i]);
        bval = m;
    }
    __syncthreads();
    mx = bval;
    __syncthreads();

    float sum = 0.0f;
#pragma unroll
    for (int i = 0; i < 16; i++) {
        v[i] = __expf(v[i] - mx);
        sum += v[i];
    }
#pragma unroll
    for (int o = 16; o > 0; o >>= 1)
        sum += __shfl_xor_sync(0xffffffffu, sum, o);
    if (lane == 0) red[warp] = sum;
    __syncthreads();
    if (tid == 0) {
        float s = 0.0f;
#pragma unroll
        for (int i = 0; i < 8; i++) s += red[i];
        bval = s;
    }
    __syncthreads();
    float inv = 1.0f / bval;
#pragma unroll
    for (int i = 0; i < 16; i++)
        p[i * 256 + tid] = rn_tf32(v[i] * inv);
}

// ---------------------------------------------------------------------------
// Launch
// ---------------------------------------------------------------------------
extern "C" void kernel_launch(void* const* d_in, const int* in_sizes, int n_in,
                              void* d_out, int out_size)
{
    const float* x  = (const float*)d_in[0];
    const float* Wq = (const float*)d_in[1];
    const float* bq = (const float*)d_in[2];
    const float* Wk = (const float*)d_in[3];
    const float* bk = (const float*)d_in[4];
    const float* Wv = (const float*)d_in[5];
    const float* bv = (const float*)d_in[6];
    float* out = (float*)d_out;

    float *Qp, *Kp, *Vtp, *Sp, *Xp, *Wp;
    cudaGetSymbolAddress((void**)&Qp,  g_Q);
    cudaGetSymbolAddress((void**)&Kp,  g_K);
    cudaGetSymbolAddress((void**)&Vtp, g_Vt);
    cudaGetSymbolAddress((void**)&Sp,  g_S);
    cudaGetSymbolAddress((void**)&Xp,  g_X);
    cudaGetSymbolAddress((void**)&Wp,  g_W);

    const int smemBytes = SMEM_F * (int)sizeof(float);     // 110592
    cudaFuncSetAttribute((const void*)tf32_gemm<false, true>,
                         cudaFuncAttributeMaxDynamicSharedMemorySize, smemBytes);
    cudaFuncSetAttribute((const void*)tf32_gemm<false, false>,
                         cudaFuncAttributeMaxDynamicSharedMemorySize, smemBytes);
    cudaFuncSetAttribute((const void*)tf32_gemm<true, true>,
                         cudaFuncAttributeMaxDynamicSharedMemorySize, smemBytes);

    const long long SH = (long long)SEQ * HIDDEN;
    const long long SS = (long long)SEQ * SEQ;
    const int WN = HIDDEN * HIDDEN;                         // 589824

    // 0) pre-round inputs to tf32-representable fp32
    {
        int n4x = BATCH * SEQ * HIDDEN / 4;                 // 3,145,728
        round_tf32_kernel<<<(n4x + 255) / 256, 256>>>((const float4*)x, (float4*)Xp, n4x);
        int n4w = WN / 4;
        round_tf32_kernel<<<(n4w + 255) / 256, 256>>>((const float4*)Wq, (float4*)(Wp), n4w);
        round_tf32_kernel<<<(n4w + 255) / 256, 256>>>((const float4*)Wk, (float4*)(Wp + WN), n4w);
        round_tf32_kernel<<<(n4w + 255) / 256, 256>>>((const float4*)Wv, (float4*)(Wp + 2 * WN), n4w);
    }

    // 1) QKV projections (per batch): [4096,768] = x_b @ W^T + b, outputs rounded.
    //    V stored transposed (Vt[b][h][s]) so the PV GEMM reads K-major B.
    {
        dim3 g(HIDDEN / BN, SEQ / BM, BATCH);   // (6, 32, 4)
        tf32_gemm<false, true><<<g, 256, smemBytes>>>(Xp, Wp, Qp, nullptr, bq,
                                                      HIDDEN, 0, HIDDEN, SH, 0, SH);
        tf32_gemm<false, true><<<g, 256, smemBytes>>>(Xp, Wp + WN, Kp, nullptr, bk,
                                                      HIDDEN, 0, HIDDEN, SH, 0, SH);
        tf32_gemm<true,  true><<<g, 256, smemBytes>>>(Xp, Wp + 2 * WN, nullptr, Vtp, bv,
                                                      HIDDEN, SEQ, HIDDEN, SH, 0, SH);
    }

    // 2) scores: S_b = Q_b @ K_b^T  (full fp32 out; rounded by softmax)
    {
        dim3 g(SEQ / BN, SEQ / BM, BATCH);      // (32, 32, 4)
        tf32_gemm<false, false><<<g, 256, smemBytes>>>(Qp, Kp, Sp, nullptr, nullptr,
                                                       SEQ, 0, HIDDEN, SH, SH, SS);
    }

    // 3) softmax rows (scale folded in, P rounded to tf32)
    {
        float scale = 1.0f / sqrtf((float)HIDDEN);
        softmax_kernel<<<BATCH * SEQ, 256>>>(Sp, scale);
    }

    // 4) output: O_b = P_b @ V_b   (Vt is [HIDDEN, SEQ] K-major, K = SEQ)
    {
        dim3 g(HIDDEN / BN, SEQ / BM, BATCH);   // (6, 32, 4)
        tf32_gemm<false, false><<<g, 256, smemBytes>>>(Sp, Vtp, out, nullptr, nullptr,
                                                       HIDDEN, 0, SEQ, SS, SH, SH);
    }
}

// round 13
// speedup vs baseline: 5.6795x; 3.9292x over previous
#include <cuda_runtime.h>
#include <cstdint>
#include <cuda_fp16.h>
#include <mma.h>

using namespace nvcuda;

#define HIDDEN 768
#define BATCH  4
#define SEQ    4096

// ---- scratch (device globals: allocation-free rule) ----
__device__ __half g_Q [BATCH * SEQ * HIDDEN];                // 24 MB
__device__ __half g_K [BATCH * SEQ * HIDDEN];                // 24 MB
__device__ __half g_Vt[BATCH * HIDDEN * SEQ];                // 24 MB (V^T per batch)
__device__ float  g_S [(long long)BATCH * SEQ * SEQ];        // 256 MB (scores, fp32)
__device__ __half g_P [(long long)BATCH * SEQ * SEQ];        // 128 MB (softmax(S), fp16)
__device__ __half g_X [BATCH * SEQ * HIDDEN];                // 24 MB (fp16 x)
__device__ __half g_W [3 * HIDDEN * HIDDEN];                 // 3.5 MB (fp16 Wq|Wk|Wv)

// ===========================================================================
// FP16 wmma GEMM (fp32 accumulate):  C[M,N] = A[M,K] @ B^T (+bias)
//   A: row-major [M,K] half;  B stored [N,K] row-major half (K-major)
// Block 128x128, 8 warps (256 thr, 2x4), warp tile 64x32.
// BK=64 (tile 128x64 half = 16KB), 3-stage cp.async pipeline.
// fp16 mantissa == tf32 mantissa (10 bits); fp32 accum -> same numerics class.
// HALF_OUT: write half (Q/K/P operands); else fp32. STORE_T: write C^T (V^T).
// ===========================================================================
constexpr int BM = 128, BN = 128, BK = 64;
constexpr int BKP = 72;                        // padded ld in halves (144B rows)

constexpr int TILE_H  = BM * BKP;              // 9216 halves = 18432 B per tile
constexpr int STAGE_H = 2 * TILE_H;            // A+B per stage
constexpr int NSTAGE  = 3;
constexpr int SMEM_B  = NSTAGE * STAGE_H * 2;  // 110592 bytes
constexpr int EPI_LD  = 36;                    // fp32 epilogue scratch ld

__device__ __forceinline__ void cp_async16(void* sdst, const void* gsrc) {
    unsigned int s = (unsigned int)__cvta_generic_to_shared(sdst);
    asm volatile("cp.async.cg.shared.global [%0], [%1], 16;\n" :: "r"(s), "l"(gsrc));
}
__device__ __forceinline__ void cp_commit() {
    asm volatile("cp.async.commit_group;\n");
}
template <int N_> __device__ __forceinline__ void cp_wait() {
    asm volatile("cp.async.wait_group %0;\n" :: "n"(N_));
}

template <bool STORE_T, bool HALF_OUT>
__global__ __launch_bounds__(256, 2)
void h_gemm(const __half* __restrict__ A, const __half* __restrict__ B,
            float* __restrict__ Cf, __half* __restrict__ Ch,
            const float* __restrict__ bias,
            int N, int ldct, int K,
            long long sA, long long sB, long long sC)
{
    extern __shared__ __half smem[];

    const int tid  = threadIdx.x;
    const int warp = tid >> 5;
    const int lane = tid & 31;
    const int m0 = blockIdx.y * BM;
    const int n0 = blockIdx.x * BN;
    const int z  = blockIdx.z;

    const __half* Ab = A + z * sA + (long long)m0 * K;
    const __half* Bb = B + z * sB + (long long)n0 * K;

    const int wm = (warp >> 2) * 64;     // 0 / 64
    const int wn = (warp & 3) * 32;      // 0/32/64/96

    wmma::fragment<wmma::accumulator, 16, 16, 16, float> acc[4][2];
#pragma unroll
    for (int i = 0; i < 4; i++)
#pragma unroll
        for (int j = 0; j < 2; j++)
            wmma::fill_fragment(acc[i][j], 0.0f);

    // ---- async loader: A[128x64]h + B[128x64]h, 16B chunks (8 halves) ----
    auto load = [&](int stage, int t) {
        __half* As = smem + stage * STAGE_H;
        __half* Bs = As + TILE_H;
        const int kb = t * BK;
#pragma unroll
        for (int i = 0; i < 4; i++) {
            int idx = tid + (i << 8);          // 0..1023
            int r = idx >> 3;                  // row 0..127
            int c = (idx & 7) << 3;            // half-offset 0,8,..,56
            cp_async16(&As[r * BKP + c], Ab + (long long)r * K + kb + c);
            cp_async16(&Bs[r * BKP + c], Bb + (long long)r * K + kb + c);
        }
        cp_commit();
    };

    const int T = K / BK;
    load(0, 0);
    load(1, 1);
    load(2, 2);

    for (int t = 0; t < T; t++) {
        const int rem = T - 1 - t;
        if (rem >= 2)      cp_wait<2>();
        else if (rem == 1) cp_wait<1>();
        else               cp_wait<0>();
        __syncthreads();

        const int st = t % 3;
        const __half* As = smem + st * STAGE_H;
        const __half* Bs = As + TILE_H;

#pragma unroll
        for (int kk = 0; kk < BK; kk += 16) {
            wmma::fragment<wmma::matrix_a, 16, 16, 16, __half, wmma::row_major> af[4];
            wmma::fragment<wmma::matrix_b, 16, 16, 16, __half, wmma::col_major> bf[2];
#pragma unroll
            for (int i = 0; i < 4; i++)
                wmma::load_matrix_sync(af[i], &As[(wm + i * 16) * BKP + kk], BKP);
#pragma unroll
            for (int j = 0; j < 2; j++)
                wmma::load_matrix_sync(bf[j], &Bs[(wn + j * 16) * BKP + kk], BKP);
#pragma unroll
            for (int i = 0; i < 4; i++)
#pragma unroll
                for (int j = 0; j < 2; j++)
                    wmma::mma_sync(acc[i][j], af[i], bf[j], acc[i][j]);
        }
        __syncthreads();
        if (t + 3 < T) load(st, t + 3);
    }

    // ---- epilogue: stage 64x32 fp32 per warp in smem, coalesced writes ----
    float* scr = (float*)smem + warp * (64 * EPI_LD);
#pragma unroll
    for (int i = 0; i < 4; i++)
#pragma unroll
        for (int j = 0; j < 2; j++)
            wmma::store_matrix_sync(&scr[(i * 16) * EPI_LD + j * 16], acc[i][j],
                                    EPI_LD, wmma::mem_row_major);
    __syncwarp();

    if constexpr (STORE_T) {
        // write C^T as half: lanes sweep m (coalesced), loop over 32 n-cols
        __half* ct = Ch + z * sC;
        const int mA = m0 + wm + lane;
        const int mB = mA + 32;
#pragma unroll 4
        for (int j = 0; j < 32; j++) {
            float bb = bias ? bias[n0 + wn + j] : 0.0f;
            long long rowo = (long long)(n0 + wn + j) * ldct;
            ct[rowo + mA] = __float2half_rn(scr[lane * EPI_LD + j] + bb);
            ct[rowo + mB] = __float2half_rn(scr[(lane + 32) * EPI_LD + j] + bb);
        }
    } else if constexpr (HALF_OUT) {
        __half* ch = Ch + z * sC;
        const float bb = bias ? bias[n0 + wn + lane] : 0.0f;
#pragma unroll 8
        for (int r = 0; r < 64; r++)
            ch[(long long)(m0 + wm + r) * N + n0 + wn + lane] =
                __float2half_rn(scr[r * EPI_LD + lane] + bb);
    } else {
        float* cf = Cf + z * sC;
        const float bb = bias ? bias[n0 + wn + lane] : 0.0f;
#pragma unroll 8
        for (int r = 0; r < 64; r++)
            cf[(long long)(m0 + wm + r) * N + n0 + wn + lane] =
                scr[r * EPI_LD + lane] + bb;
    }
}

// ---------------------------------------------------------------------------
// Convert fp32 -> fp16 (RN), vectorized: float4 in, 4 halves (uint2) out.
// ---------------------------------------------------------------------------
__global__ void to_half_kernel(const float4* __restrict__ in,
                               __half2* __restrict__ out, int n4)
{
    int i = blockIdx.x * blockDim.x + threadIdx.x;
    if (i >= n4) return;
    float4 v = in[i];
    out[2 * i]     = __floats2half2_rn(v.x, v.y);
    out[2 * i + 1] = __floats2half2_rn(v.z, v.w);
}

// ---------------------------------------------------------------------------
// Row softmax over SEQ=4096 (scale folded); reads fp32 S, writes fp16 P.
// One block (256 thr) per row.
// ---------------------------------------------------------------------------
__global__ __launch_bounds__(256)
void softmax_kernel(const float* __restrict__ S, __half* __restrict__ P, float scale)
{
    long long row = blockIdx.x;
    const float* p = S + row * (long long)SEQ;
    __half* q = P + row * (long long)SEQ;
    const int tid  = threadIdx.x;
    const int warp = tid >> 5;
    const int lane = tid & 31;

    __shared__ float red[8];
    __shared__ float bval;

    float v[16];
    float mx = -1e30f;
#pragma unroll
    for (int i = 0; i < 16; i++) {
        v[i] = p[i * 256 + tid] * scale;
        mx = fmaxf(mx, v[i]);
    }
#pragma unroll
    for (int o = 16; o > 0; o >>= 1)
        mx = fmaxf(mx, __shfl_xor_sync(0xffffffffu, mx, o));
    if (lane == 0) red[warp] = mx;
    __syncthreads();
    if (tid == 0) {
        float m = red[0];
#pragma unroll
        for (int i = 1; i < 8; i++) m = fmaxf(m, red[i]);
        bval = m;
    }
    __syncthreads();
    mx = bval;
    __syncthreads();

    float sum = 0.0f;
#pragma unroll
    for (int i = 0; i < 16; i++) {
        v[i] = __expf(v[i] - mx);
        sum += v[i];
    }
#pragma unroll
    for (int o = 16; o > 0; o >>= 1)
        sum += __shfl_xor_sync(0xffffffffu, sum, o);
    if (lane == 0) red[warp] = sum;
    __syncthreads();
    if (tid == 0) {
        float s = 0.0f;
#pragma unroll
        for (int i = 0; i < 8; i++) s += red[i];
        bval = s;
    }
    __syncthreads();
    float inv = 1.0f / bval;
#pragma unroll
    for (int i = 0; i < 16; i++)
        q[i * 256 + tid] = __float2half_rn(v[i] * inv);
}

// ---------------------------------------------------------------------------
// Launch
// ---------------------------------------------------------------------------
extern "C" void kernel_launch(void* const* d_in, const int* in_sizes, int n_in,
                              void* d_out, int out_size)
{
    const float* x  = (const float*)d_in[0];
    const float* Wq = (const float*)d_in[1];
    const float* bq = (const float*)d_in[2];
    const float* Wk = (const float*)d_in[3];
    const float* bk = (const float*)d_in[4];
    const float* Wv = (const float*)d_in[5];
    const float* bv = (const float*)d_in[6];
    float* out = (float*)d_out;

    __half *Qp, *Kp, *Vtp, *Pp, *Xp, *Wp;
    float  *Sp;
    cudaGetSymbolAddress((void**)&Qp,  g_Q);
    cudaGetSymbolAddress((void**)&Kp,  g_K);
    cudaGetSymbolAddress((void**)&Vtp, g_Vt);
    cudaGetSymbolAddress((void**)&Sp,  g_S);
    cudaGetSymbolAddress((void**)&Pp,  g_P);
    cudaGetSymbolAddress((void**)&Xp,  g_X);
    cudaGetSymbolAddress((void**)&Wp,  g_W);

    cudaFuncSetAttribute((const void*)h_gemm<false, true>,
                         cudaFuncAttributeMaxDynamicSharedMemorySize, SMEM_B);
    cudaFuncSetAttribute((const void*)h_gemm<false, false>,
                         cudaFuncAttributeMaxDynamicSharedMemorySize, SMEM_B);
    cudaFuncSetAttribute((const void*)h_gemm<true, true>,
                         cudaFuncAttributeMaxDynamicSharedMemorySize, SMEM_B);

    const long long SH = (long long)SEQ * HIDDEN;
    const long long SS = (long long)SEQ * SEQ;
    const int WN = HIDDEN * HIDDEN;                         // 589824

    // 0) convert inputs to fp16
    {
        int n4x = BATCH * SEQ * HIDDEN / 4;                 // 3,145,728
        to_half_kernel<<<(n4x + 255) / 256, 256>>>((const float4*)x, (__half2*)Xp, n4x);
        int n4w = WN / 4;
        to_half_kernel<<<(n4w + 255) / 256, 256>>>((const float4*)Wq, (__half2*)(Wp), n4w);
        to_half_kernel<<<(n4w + 255) / 256, 256>>>((const float4*)Wk, (__half2*)(Wp + WN), n4w);
        to_half_kernel<<<(n4w + 255) / 256, 256>>>((const float4*)Wv, (__half2*)(Wp + 2 * WN), n4w);
    }

    // 1) QKV projections (per batch): fp16 out (bias added in fp32).
    //    V stored transposed (Vt[b][h][s]) so the PV GEMM reads K-major B.
    {
        dim3 g(HIDDEN / BN, SEQ / BM, BATCH);   // (6, 32, 4)
        h_gemm<false, true><<<g, 256, SMEM_B>>>(Xp, Wp, nullptr, Qp, bq,
                                                HIDDEN, 0, HIDDEN, SH, 0, SH);
        h_gemm<false, true><<<g, 256, SMEM_B>>>(Xp, Wp + WN, nullptr, Kp, bk,
                                                HIDDEN, 0, HIDDEN, SH, 0, SH);
        h_gemm<true,  true><<<g, 256, SMEM_B>>>(Xp, Wp + 2 * WN, nullptr, Vtp, bv,
                                                HIDDEN, SEQ, HIDDEN, SH, 0, SH);
    }

    // 2) scores: S_b = Q_b @ K_b^T  (fp32 out)
    {
        dim3 g(SEQ / BN, SEQ / BM, BATCH);      // (32, 32, 4)
        h_gemm<false, false><<<g, 256, SMEM_B>>>(Qp, Kp, Sp, nullptr, nullptr,
                                                 SEQ, 0, HIDDEN, SH, SH, SS);
    }

    // 3) softmax rows: fp32 S -> fp16 P (scale folded in)
    {
        float scale = 1.0f / sqrtf((float)HIDDEN);
        softmax_kernel<<<BATCH * SEQ, 256>>>(Sp, Pp, scale);
    }

    // 4) output: O_b = P_b @ V_b   (Vt is [HIDDEN, SEQ] K-major, K = SEQ), fp32 out
    {
        dim3 g(HIDDEN / BN, SEQ / BM, BATCH);   // (6, 32, 4)
        h_gemm<false, false><<<g, 256, SMEM_B>>>(Pp, Vtp, out, nullptr, nullptr,
                                                 HIDDEN, 0, SEQ, SS, SH, SH);
    }
}

// round 14
// speedup vs baseline: 5.9441x; 1.0466x over previous
#include <cuda_runtime.h>
#include <cstdint>
#include <cuda_fp16.h>
#include <mma.h>

using namespace nvcuda;

#define HIDDEN 768
#define BATCH  4
#define SEQ    4096

// ---- scratch (device globals: allocation-free rule) ----
__device__ __half g_Q [BATCH * SEQ * HIDDEN];                // 24 MB (scale pre-folded)
__device__ __half g_K [BATCH * SEQ * HIDDEN];                // 24 MB
__device__ __half g_Vt[BATCH * HIDDEN * SEQ];                // 24 MB (V^T per batch)
__device__ __half g_S [(long long)BATCH * SEQ * SEQ];        // 128 MB (S then P, in place)
__device__ __half g_X [BATCH * SEQ * HIDDEN];                // 24 MB (fp16 x)
__device__ __half g_W [3 * HIDDEN * HIDDEN];                 // 3.5 MB (fp16 Wq|Wk|Wv)

// ===========================================================================
// FP16 wmma GEMM (fp32 accumulate):  C[M,N] = A[M,K] @ B^T (+bias)
// Block 128x128, 8 warps (256 thr, 2x4), warp tile 64x32, BK=64,
// 3-stage cp.async pipeline. HALF_OUT: fp16 C; else fp32 C.
// ===========================================================================
constexpr int BM = 128, BN = 128, BK = 64;
constexpr int BKP = 72;                        // padded ld in halves (144B rows)

constexpr int TILE_H  = BM * BKP;              // 9216 halves per tile
constexpr int STAGE_H = 2 * TILE_H;            // A+B per stage
constexpr int NSTAGE  = 3;
constexpr int SMEM_B  = NSTAGE * STAGE_H * 2;  // 110592 bytes
constexpr int EPI_LD  = 36;                    // fp32 epilogue scratch ld

__device__ __forceinline__ void cp_async16(void* sdst, const void* gsrc) {
    unsigned int s = (unsigned int)__cvta_generic_to_shared(sdst);
    asm volatile("cp.async.cg.shared.global [%0], [%1], 16;\n" :: "r"(s), "l"(gsrc));
}
__device__ __forceinline__ void cp_commit() {
    asm volatile("cp.async.commit_group;\n");
}
template <int N_> __device__ __forceinline__ void cp_wait() {
    asm volatile("cp.async.wait_group %0;\n" :: "n"(N_));
}

// ---- shared mainloop: fills acc[4][2] for this CTA/warp ----
template <typename AccT>
__device__ __forceinline__ void gemm_mainloop(
    const __half* __restrict__ Ab, const __half* __restrict__ Bb,
    __half* smem, int K, int tid, int wm, int wn, AccT acc[4][2])
{
    auto load = [&](int stage, int t) {
        __half* As = smem + stage * STAGE_H;
        __half* Bs = As + TILE_H;
        const int kb = t * BK;
#pragma unroll
        for (int i = 0; i < 4; i++) {
            int idx = tid + (i << 8);
            int r = idx >> 3;
            int c = (idx & 7) << 3;
            cp_async16(&As[r * BKP + c], Ab + (long long)r * K + kb + c);
            cp_async16(&Bs[r * BKP + c], Bb + (long long)r * K + kb + c);
        }
        cp_commit();
    };

    const int T = K / BK;
    load(0, 0);
    load(1, 1);
    load(2, 2);

    for (int t = 0; t < T; t++) {
        const int rem = T - 1 - t;
        if (rem >= 2)      cp_wait<2>();
        else if (rem == 1) cp_wait<1>();
        else               cp_wait<0>();
        __syncthreads();

        const int st = t % 3;
        const __half* As = smem + st * STAGE_H;
        const __half* Bs = As + TILE_H;

#pragma unroll
        for (int kk = 0; kk < BK; kk += 16) {
            wmma::fragment<wmma::matrix_a, 16, 16, 16, __half, wmma::row_major> af[4];
            wmma::fragment<wmma::matrix_b, 16, 16, 16, __half, wmma::col_major> bf[2];
#pragma unroll
            for (int i = 0; i < 4; i++)
                wmma::load_matrix_sync(af[i], &As[(wm + i * 16) * BKP + kk], BKP);
#pragma unroll
            for (int j = 0; j < 2; j++)
                wmma::load_matrix_sync(bf[j], &Bs[(wn + j * 16) * BKP + kk], BKP);
#pragma unroll
            for (int i = 0; i < 4; i++)
#pragma unroll
                for (int j = 0; j < 2; j++)
                    wmma::mma_sync(acc[i][j], af[i], bf[j], acc[i][j]);
        }
        __syncthreads();
        if (t + 3 < T) load(st, t + 3);
    }
}

// ---- generic GEMM: scores (HALF_OUT) and PV (fp32 out) ----
template <bool HALF_OUT>
__global__ __launch_bounds__(256, 2)
void h_gemm(const __half* __restrict__ A, const __half* __restrict__ B,
            float* __restrict__ Cf, __half* __restrict__ Ch,
            int N, int K,
            long long sA, long long sB, long long sC)
{
    extern __shared__ __half smem[];
    const int tid  = threadIdx.x;
    const int warp = tid >> 5;
    const int lane = tid & 31;
    const int m0 = blockIdx.y * BM;
    const int n0 = blockIdx.x * BN;
    const int z  = blockIdx.z;
    const int wm = (warp >> 2) * 64;
    const int wn = (warp & 3) * 32;

    const __half* Ab = A + z * sA + (long long)m0 * K;
    const __half* Bb = B + z * sB + (long long)n0 * K;

    wmma::fragment<wmma::accumulator, 16, 16, 16, float> acc[4][2];
#pragma unroll
    for (int i = 0; i < 4; i++)
#pragma unroll
        for (int j = 0; j < 2; j++)
            wmma::fill_fragment(acc[i][j], 0.0f);

    gemm_mainloop(Ab, Bb, smem, K, tid, wm, wn, acc);

    float* scr = (float*)smem + warp * (64 * EPI_LD);
#pragma unroll
    for (int i = 0; i < 4; i++)
#pragma unroll
        for (int j = 0; j < 2; j++)
            wmma::store_matrix_sync(&scr[(i * 16) * EPI_LD + j * 16], acc[i][j],
                                    EPI_LD, wmma::mem_row_major);
    __syncwarp();

    if constexpr (HALF_OUT) {
        __half* ch = Ch + z * sC;
#pragma unroll 8
        for (int r = 0; r < 64; r++)
            ch[(long long)(m0 + wm + r) * N + n0 + wn + lane] =
                __float2half_rn(scr[r * EPI_LD + lane]);
    } else {
        float* cf = Cf + z * sC;
#pragma unroll 8
        for (int r = 0; r < 64; r++)
            cf[(long long)(m0 + wm + r) * N + n0 + wn + lane] =
                scr[r * EPI_LD + lane];
    }
}

// ---- fused QKV: grid.z = 12 -> (w = z>>2: 0=Q,1=K,2=V ; b = z&3) ----
__global__ __launch_bounds__(256, 2)
void qkv_kernel(const __half* __restrict__ X, const __half* __restrict__ W3,
                __half* __restrict__ Q, __half* __restrict__ Kh,
                __half* __restrict__ Vt,
                const float* __restrict__ bq, const float* __restrict__ bk,
                const float* __restrict__ bv, float qscale)
{
    extern __shared__ __half smem[];
    const int tid  = threadIdx.x;
    const int warp = tid >> 5;
    const int lane = tid & 31;
    const int m0 = blockIdx.y * BM;
    const int n0 = blockIdx.x * BN;
    const int w  = blockIdx.z >> 2;          // 0=Q, 1=K, 2=V
    const int b  = blockIdx.z & 3;
    const int wm = (warp >> 2) * 64;
    const int wn = (warp & 3) * 32;

    const long long SH = (long long)SEQ * HIDDEN;
    const int WN = HIDDEN * HIDDEN;

    const __half* Ab = X + b * SH + (long long)m0 * HIDDEN;
    const __half* Bb = W3 + w * WN + (long long)n0 * HIDDEN;

    wmma::fragment<wmma::accumulator, 16, 16, 16, float> acc[4][2];
#pragma unroll
    for (int i = 0; i < 4; i++)
#pragma unroll
        for (int j = 0; j < 2; j++)
            wmma::fill_fragment(acc[i][j], 0.0f);

    gemm_mainloop(Ab, Bb, smem, HIDDEN, tid, wm, wn, acc);

    float* scr = (float*)smem + warp * (64 * EPI_LD);
#pragma unroll
    for (int i = 0; i < 4; i++)
#pragma unroll
        for (int j = 0; j < 2; j++)
            wmma::store_matrix_sync(&scr[(i * 16) * EPI_LD + j * 16], acc[i][j],
                                    EPI_LD, wmma::mem_row_major);
    __syncwarp();

    if (w == 2) {
        // V: transposed store -> Vt[b][h][s]; lanes sweep m (coalesced)
        __half* ct = Vt + b * SH;
        const int mA = m0 + wm + lane;
        const int mB = mA + 32;
#pragma unroll 4
        for (int j = 0; j < 32; j++) {
            float bb = bv[n0 + wn + j];
            long long rowo = (long long)(n0 + wn + j) * SEQ;
            ct[rowo + mA] = __float2half_rn(scr[lane * EPI_LD + j] + bb);
            ct[rowo + mB] = __float2half_rn(scr[(lane + 32) * EPI_LD + j] + bb);
        }
    } else {
        __half* ch = (w == 0 ? Q : Kh) + b * SH;
        const float* bias = (w == 0 ? bq : bk);
        const float sc = (w == 0 ? qscale : 1.0f);
        const float bb = bias[n0 + wn + lane];
#pragma unroll 8
        for (int r = 0; r < 64; r++)
            ch[(long long)(m0 + wm + r) * HIDDEN + n0 + wn + lane] =
                __float2half_rn((scr[r * EPI_LD + lane] + bb) * sc);
    }
}

// ---------------------------------------------------------------------------
// Convert fp32 -> fp16 (RN), vectorized.
// ---------------------------------------------------------------------------
__global__ void to_half_kernel(const float4* __restrict__ in,
                               __half2* __restrict__ out, int n4)
{
    int i = blockIdx.x * blockDim.x + threadIdx.x;
    if (i >= n4) return;
    float4 v = in[i];
    out[2 * i]     = __floats2half2_rn(v.x, v.y);
    out[2 * i + 1] = __floats2half2_rn(v.z, v.w);
}

// ---------------------------------------------------------------------------
// In-place row softmax over SEQ=4096 fp16 (scale pre-folded into Q).
// One block (256 thr) per row; half2 vectorized, fp32 math.
// ---------------------------------------------------------------------------
__global__ __launch_bounds__(256)
void softmax_kernel(__half* __restrict__ S)
{
    long long row = blockIdx.x;
    __half2* p = (__half2*)(S + row * (long long)SEQ);
    const int tid  = threadIdx.x;
    const int warp = tid >> 5;
    const int lane = tid & 31;

    __shared__ float red[8];
    __shared__ float bval;

    float v[16];
    float mx = -1e30f;
#pragma unroll
    for (int i = 0; i < 8; i++) {
        float2 f = __half22float2(p[i * 256 + tid]);
        v[2 * i] = f.x; v[2 * i + 1] = f.y;
        mx = fmaxf(mx, fmaxf(f.x, f.y));
    }
#pragma unroll
    for (int o = 16; o > 0; o >>= 1)
        mx = fmaxf(mx, __shfl_xor_sync(0xffffffffu, mx, o));
    if (lane == 0) red[warp] = mx;
    __syncthreads();
    if (tid == 0) {
        float m = red[0];
#pragma unroll
        for (int i = 1; i < 8; i++) m = fmaxf(m, red[i]);
        bval = m;
    }
    __syncthreads();
    mx = bval;
    __syncthreads();

    float sum = 0.0f;
#pragma unroll
    for (int i = 0; i < 16; i++) {
        v[i] = __expf(v[i] - mx);
        sum += v[i];
    }
#pragma unroll
    for (int o = 16; o > 0; o >>= 1)
        sum += __shfl_xor_sync(0xffffffffu, sum, o);
    if (lane == 0) red[warp] = sum;
    __syncthreads();
    if (tid == 0) {
        float s = 0.0f;
#pragma unroll
        for (int i = 0; i < 8; i++) s += red[i];
        bval = s;
    }
    __syncthreads();
    float inv = 1.0f / bval;
#pragma unroll
    for (int i = 0; i < 8; i++)
        p[i * 256 + tid] = __floats2half2_rn(v[2 * i] * inv, v[2 * i + 1] * inv);
}

// ---------------------------------------------------------------------------
// Launch
// ---------------------------------------------------------------------------
extern "C" void kernel_launch(void* const* d_in, const int* in_sizes, int n_in,
                              void* d_out, int out_size)
{
    const float* x  = (const float*)d_in[0];
    const float* Wq = (const float*)d_in[1];
    const float* bq = (const float*)d_in[2];
    const float* Wk = (const float*)d_in[3];
    const float* bk = (const float*)d_in[4];
    const float* Wv = (const float*)d_in[5];
    const float* bv = (const float*)d_in[6];
    float* out = (float*)d_out;

    __half *Qp, *Kp, *Vtp, *Sp, *Xp, *Wp;
    cudaGetSymbolAddress((void**)&Qp,  g_Q);
    cudaGetSymbolAddress((void**)&Kp,  g_K);
    cudaGetSymbolAddress((void**)&Vtp, g_Vt);
    cudaGetSymbolAddress((void**)&Sp,  g_S);
    cudaGetSymbolAddress((void**)&Xp,  g_X);
    cudaGetSymbolAddress((void**)&Wp,  g_W);

    cudaFuncSetAttribute((const void*)h_gemm<true>,
                         cudaFuncAttributeMaxDynamicSharedMemorySize, SMEM_B);
    cudaFuncSetAttribute((const void*)h_gemm<false>,
                         cudaFuncAttributeMaxDynamicSharedMemorySize, SMEM_B);
    cudaFuncSetAttribute((const void*)qkv_kernel,
                         cudaFuncAttributeMaxDynamicSharedMemorySize, SMEM_B);

    const long long SH = (long long)SEQ * HIDDEN;
    const long long SS = (long long)SEQ * SEQ;
    const int WN = HIDDEN * HIDDEN;

    // 0) convert inputs to fp16
    {
        int n4x = BATCH * SEQ * HIDDEN / 4;
        to_half_kernel<<<(n4x + 255) / 256, 256>>>((const float4*)x, (__half2*)Xp, n4x);
        int n4w = WN / 4;
        to_half_kernel<<<(n4w + 255) / 256, 256>>>((const float4*)Wq, (__half2*)(Wp), n4w);
        to_half_kernel<<<(n4w + 255) / 256, 256>>>((const float4*)Wk, (__half2*)(Wp + WN), n4w);
        to_half_kernel<<<(n4w + 255) / 256, 256>>>((const float4*)Wv, (__half2*)(Wp + 2 * WN), n4w);
    }

    // 1) fused QKV: one launch, grid.z = 12 (3 weights x 4 batches).
    //    Q gets softmax scale folded in; V stored transposed.
    {
        float qscale = 1.0f / sqrtf((float)HIDDEN);
        dim3 g(HIDDEN / BN, SEQ / BM, 12);      // (6, 32, 12)
        qkv_kernel<<<g, 256, SMEM_B>>>(Xp, Wp, Qp, Kp, Vtp, bq, bk, bv, qscale);
    }

    // 2+3) per batch: scores_b (fp16 S, scaled) then in-place softmax_b.
    //      S_b is 32 MB fp16 -> L2-resident between the two launches.
    for (int b = 0; b < BATCH; b++) {
        dim3 g(SEQ / BN, SEQ / BM, 1);          // (32, 32)
        h_gemm<true><<<g, 256, SMEM_B>>>(Qp + b * SH, Kp + b * SH,
                                         nullptr, Sp + b * SS,
                                         SEQ, HIDDEN, 0, 0, 0);
        softmax_kernel<<<SEQ, 256>>>(Sp + b * SS);
    }

    // 4) output: O_b = P_b @ V_b   (Vt is [HIDDEN, SEQ] K-major, K = SEQ)
    {
        dim3 g(HIDDEN / BN, SEQ / BM, BATCH);   // (6, 32, 4)
        h_gemm<false><<<g, 256, SMEM_B>>>(Sp, Vtp, out, nullptr,
                                          HIDDEN, SEQ, SS, SH, SH);
    }
}